// round 5
// baseline (speedup 1.0000x reference)
#include <cuda_runtime.h>
#include <cstdint>

#define HASH_SIZE (1u << 19)
#define HASH_MASK (HASH_SIZE - 1u)
#define PRIME_X 73856093u
#define PRIME_Y 19349663u
#define UNROLL 4

// One position row = 32 floats = 8 float4 = 128 bytes.
// 8 threads cooperate per row: thread j moves float4 #j.
// Each thread handles UNROLL rows (strided by total group count):
// 4 independent position loads -> 4 hashes -> 4 independent gathers.
// __launch_bounds__(256, 8) caps regs at 32 -> 8 blocks/SM -> 100% occupancy;
// R3/R4 showed warp count beats per-thread MLP beyond ~4 for this kernel.
__global__ void __launch_bounds__(256, 8)
hashgrid_gather_kernel(const float2* __restrict__ positions,
                       const float4* __restrict__ table,
                       float4* __restrict__ out,
                       int n) {
    int gid     = blockIdx.x * blockDim.x + threadIdx.x;
    int part    = gid & 7;
    int group   = gid >> 3;
    int ngroups = (gridDim.x * blockDim.x) >> 3;

    int      r[UNROLL];
    float2   p[UNROLL];
    uint32_t h[UNROLL];
    float4   v[UNROLL];

    // Phase 1: batch all position loads (independent -> front-batched LDGs)
    #pragma unroll
    for (int u = 0; u < UNROLL; u++) {
        r[u] = group + u * ngroups;
        if (r[u] < n) p[u] = __ldg(&positions[r[u]]);
    }

    // Phase 2: hashes (ALU only). Low 19 bits of the int64 products depend
    // only on the low 32 bits -> uint32 math reproduces the reference exactly.
    // floorf is exact for uniform [0, 4096) positions.
    #pragma unroll
    for (int u = 0; u < UNROLL; u++) {
        uint32_t ix = (uint32_t)(int)floorf(p[u].x);
        uint32_t iy = (uint32_t)(int)floorf(p[u].y);
        h[u] = ((ix * PRIME_X) ^ (iy * PRIME_Y)) & HASH_MASK;
    }

    // Phase 3: batch all gathers (independent, mostly L2 hits)
    #pragma unroll
    for (int u = 0; u < UNROLL; u++) {
        if (r[u] < n) v[u] = __ldg(&table[(size_t)h[u] * 8 + part]);
    }

    // Phase 4: coalesced stores
    #pragma unroll
    for (int u = 0; u < UNROLL; u++) {
        if (r[u] < n) out[(size_t)r[u] * 8 + part] = v[u];
    }
}

extern "C" void kernel_launch(void* const* d_in, const int* in_sizes, int n_in,
                              void* d_out, int out_size) {
    const float2* positions = (const float2*)d_in[0];   // [N, 2] float32
    const float4* table     = (const float4*)d_in[1];   // [HASH_SIZE, 32] float32
    float4* out             = (float4*)d_out;           // [N, 32] float32

    int n = in_sizes[0] / 2;                 // N positions
    int ngroups = (n + UNROLL - 1) / UNROLL; // position groups (rows per thread-slot)
    long long total_threads = (long long)ngroups * 8;
    int block = 256;
    int grid = (int)((total_threads + block - 1) / block);

    hashgrid_gather_kernel<<<grid, block>>>(positions, table, out, n);
}

// round 9
// speedup vs baseline: 1.1175x; 1.1175x over previous
#include <cuda_runtime.h>
#include <cstdint>

#define HASH_SIZE (1u << 19)
#define HASH_MASK (HASH_SIZE - 1u)
#define PRIME_X 73856093u
#define PRIME_Y 19349663u
#define UNROLL 4

// Table gather with L2 evict_last via createpolicy + cache_hint (the direct
// .L2::evict_last modifier requires v8.b32 on sm_103a; the policy form takes v4).
__device__ __forceinline__ float4 ldg_evict_last(const float4* p, uint64_t pol) {
    float4 v;
    asm volatile("ld.global.nc.L2::cache_hint.v4.f32 {%0,%1,%2,%3}, [%4], %5;"
                 : "=f"(v.x), "=f"(v.y), "=f"(v.z), "=f"(v.w)
                 : "l"(p), "l"(pol));
    return v;
}

// One position row = 32 floats = 8 float4 = 128 bytes.
// 8 threads cooperate per row: thread j moves float4 #j.
// Each thread handles UNROLL rows (strided by total group count):
// 4 independent position loads -> 4 hashes -> 4 independent gathers.
// R3-R5 established: no launch_bounds (40 regs keeps MLP 4 intact),
// UNROLL 4 (warp count beats per-thread MLP beyond 4).
__global__ void hashgrid_gather_kernel(const float2* __restrict__ positions,
                                       const float4* __restrict__ table,
                                       float4* __restrict__ out,
                                       int n) {
    int gid     = blockIdx.x * blockDim.x + threadIdx.x;
    int part    = gid & 7;
    int group   = gid >> 3;
    int ngroups = (gridDim.x * blockDim.x) >> 3;

    // Evict-last policy: keep table lines resident in L2 against the
    // 256MB write-once output stream.
    uint64_t pol;
    asm volatile("createpolicy.fractional.L2::evict_last.b64 %0, 1.0;" : "=l"(pol));

    int      r[UNROLL];
    float2   p[UNROLL];
    uint32_t h[UNROLL];
    float4   v[UNROLL];

    // Phase 1: batch all position loads (independent -> front-batched LDGs)
    #pragma unroll
    for (int u = 0; u < UNROLL; u++) {
        r[u] = group + u * ngroups;
        if (r[u] < n) p[u] = __ldg(&positions[r[u]]);
    }

    // Phase 2: hashes (ALU only). Low 19 bits of the int64 products depend
    // only on the low 32 bits -> uint32 math reproduces the reference exactly.
    // floorf is exact for uniform [0, 4096) positions.
    #pragma unroll
    for (int u = 0; u < UNROLL; u++) {
        uint32_t ix = (uint32_t)(int)floorf(p[u].x);
        uint32_t iy = (uint32_t)(int)floorf(p[u].y);
        h[u] = ((ix * PRIME_X) ^ (iy * PRIME_Y)) & HASH_MASK;
    }

    // Phase 3: batch all gathers (independent, L2 hits; evict_last pins table)
    #pragma unroll
    for (int u = 0; u < UNROLL; u++) {
        if (r[u] < n) v[u] = ldg_evict_last(&table[(size_t)h[u] * 8 + part], pol);
    }

    // Phase 4: coalesced streaming stores (evict-first; output never re-read)
    #pragma unroll
    for (int u = 0; u < UNROLL; u++) {
        if (r[u] < n) __stcs(&out[(size_t)r[u] * 8 + part], v[u]);
    }
}

extern "C" void kernel_launch(void* const* d_in, const int* in_sizes, int n_in,
                              void* d_out, int out_size) {
    const float2* positions = (const float2*)d_in[0];   // [N, 2] float32
    const float4* table     = (const float4*)d_in[1];   // [HASH_SIZE, 32] float32
    float4* out             = (float4*)d_out;           // [N, 32] float32

    int n = in_sizes[0] / 2;                 // N positions
    int ngroups = (n + UNROLL - 1) / UNROLL; // position groups (rows per thread-slot)
    long long total_threads = (long long)ngroups * 8;
    int block = 256;
    int grid = (int)((total_threads + block - 1) / block);

    hashgrid_gather_kernel<<<grid, block>>>(positions, table, out, n);
}

// round 10
// speedup vs baseline: 1.1513x; 1.0303x over previous
#include <cuda_runtime.h>
#include <cstdint>

#define HASH_SIZE (1u << 19)
#define HASH_MASK (HASH_SIZE - 1u)
#define PRIME_X 73856093u
#define PRIME_Y 19349663u
#define ROWS_PER_BLOCK 256     // 256 rows x 128B = 32KB smem staging
#define UNROLL 8               // rows per thread-slot (256 thr, 8 thr/row)

// Decoupled gather: cp.async (no result registers -> MLP 8 per thread is free,
// occupancy stays high) stages table rows in smem; one bulk TMA store pushes
// the 32KB tile to the contiguous output range. Breaks the register/MLP
// coupling that capped R3-R5 at occ 62% x MLP 4.
__global__ void __launch_bounds__(256)
hashgrid_gather_kernel(const float2* __restrict__ positions,
                       const float4* __restrict__ table,
                       float4* __restrict__ out,
                       int n) {
    __shared__ __align__(128) float4 buf[ROWS_PER_BLOCK * 8];  // 32 KB

    int tid   = threadIdx.x;
    int part  = tid & 7;          // which float4 of the 128B row
    int lgrp  = tid >> 3;         // local row group 0..31
    int base  = blockIdx.x * ROWS_PER_BLOCK;

    uint32_t smem_base = (uint32_t)__cvta_generic_to_shared(buf);

    int      r[UNROLL];
    float2   p[UNROLL];
    uint32_t h[UNROLL];

    // Phase 1: batch position loads (independent -> front-batched LDGs)
    #pragma unroll
    for (int u = 0; u < UNROLL; u++) {
        r[u] = base + lgrp + u * 32;
        if (r[u] < n) p[u] = __ldg(&positions[r[u]]);
    }

    // Phase 2: hashes. Low 19 bits of the int64 products depend only on the
    // low 32 bits -> uint32 math reproduces the reference exactly; floorf is
    // exact for uniform [0, 4096) positions.
    #pragma unroll
    for (int u = 0; u < UNROLL; u++) {
        uint32_t ix = (uint32_t)(int)floorf(p[u].x);
        uint32_t iy = (uint32_t)(int)floorf(p[u].y);
        h[u] = ((ix * PRIME_X) ^ (iy * PRIME_Y)) & HASH_MASK;
    }

    // Phase 3: 8 independent 16B cp.async gathers per thread (no result regs)
    #pragma unroll
    for (int u = 0; u < UNROLL; u++) {
        if (r[u] < n) {
            const float4* src = &table[(size_t)h[u] * 8 + part];
            uint32_t dst = smem_base + (uint32_t)(((lgrp + u * 32) * 8 + part) * 16);
            asm volatile("cp.async.cg.shared.global [%0], [%1], 16;"
                         :: "r"(dst), "l"(src));
        }
    }
    asm volatile("cp.async.commit_group;");
    asm volatile("cp.async.wait_group 0;");
    asm volatile("fence.proxy.async.shared::cta;" ::: "memory");
    __syncthreads();

    // Phase 4: single bulk async store of the whole contiguous tile
    if (tid == 0) {
        int rows = n - base;
        rows = rows < ROWS_PER_BLOCK ? rows : ROWS_PER_BLOCK;
        if (rows > 0) {
            uint32_t bytes = (uint32_t)rows * 128u;
            asm volatile("cp.async.bulk.global.shared::cta.bulk_group [%0], [%1], %2;"
                         :: "l"(out + (size_t)base * 8), "r"(smem_base), "r"(bytes)
                         : "memory");
            asm volatile("cp.async.bulk.commit_group;");
            asm volatile("cp.async.bulk.wait_group 0;" ::: "memory");
        }
    }
}

extern "C" void kernel_launch(void* const* d_in, const int* in_sizes, int n_in,
                              void* d_out, int out_size) {
    const float2* positions = (const float2*)d_in[0];   // [N, 2] float32
    const float4* table     = (const float4*)d_in[1];   // [HASH_SIZE, 32] float32
    float4* out             = (float4*)d_out;           // [N, 32] float32

    int n = in_sizes[0] / 2;    // N positions
    int grid = (n + ROWS_PER_BLOCK - 1) / ROWS_PER_BLOCK;

    hashgrid_gather_kernel<<<grid, 256>>>(positions, table, out, n);
}